// round 16
// baseline (speedup 1.0000x reference)
#include <cuda_runtime.h>
#include <cuda_bf16.h>
#include <math.h>
#include <stdint.h>

#define NB 2
#define LQ 1024
#define DM 4544
#define HH 71
#define DKVD 64
#define QKVN 4672            /* 73*64 */
#define MROWS 2048
#define KDIM 4544            /* 71*64 */

// ---------------------------------------------------------------------------
// Scratch (static device globals — no allocation)
// ---------------------------------------------------------------------------
__device__ float g_qkv[(size_t)MROWS * QKVN];   // [2048, 4672] fp32 (QKV GEMM out)

__device__ __align__(256) __nv_bfloat16 g_hid_hi[(size_t)MROWS * KDIM];
__device__ __align__(256) __nv_bfloat16 g_hid_lo[(size_t)MROWS * KDIM];
__device__ __align__(256) __nv_bfloat16 g_wq_hi [(size_t)QKVN  * KDIM];
__device__ __align__(256) __nv_bfloat16 g_wq_lo [(size_t)QKVN  * KDIM];
__device__ __align__(256) __nv_bfloat16 g_wd_hi [(size_t)DM    * KDIM];
__device__ __align__(256) __nv_bfloat16 g_wd_lo [(size_t)DM    * KDIM];
__device__ __align__(256) __nv_bfloat16 g_att_hi[(size_t)MROWS * DM];
__device__ __align__(256) __nv_bfloat16 g_att_lo[(size_t)MROWS * DM];

// bf16 hi/lo attention operands (written by prep kernel)
__device__ __align__(256) __nv_bfloat16 g_q_hi[(size_t)NB * HH * LQ * DKVD]; // [n][h][pos][64]
__device__ __align__(256) __nv_bfloat16 g_q_lo[(size_t)NB * HH * LQ * DKVD];
__device__ __align__(256) __nv_bfloat16 g_k_hi[(size_t)NB * LQ * DKVD];      // [n][pos][64]
__device__ __align__(256) __nv_bfloat16 g_k_lo[(size_t)NB * LQ * DKVD];
__device__ __align__(256) __nv_bfloat16 g_v_hi[(size_t)NB * LQ * DKVD];
__device__ __align__(256) __nv_bfloat16 g_v_lo[(size_t)NB * LQ * DKVD];

// ---------------------------------------------------------------------------
// Helpers (baseline PTX ISA only — NO tcgen05 / no accel features)
// ---------------------------------------------------------------------------
__device__ __forceinline__ uint32_t smem_u32(const void* p) {
    uint32_t a;
    asm("{ .reg .u64 t; cvta.to.shared.u64 t, %1; cvt.u32.u64 %0, t; }"
        : "=r"(a) : "l"(p));
    return a;
}

#define CP_ASYNC16(smem, gptr) \
    asm volatile("cp.async.cg.shared.global [%0], [%1], 16;" \
                 :: "r"(smem), "l"(gptr) : "memory")
#define CP_COMMIT() asm volatile("cp.async.commit_group;" ::: "memory")
#define CP_WAIT1()  asm volatile("cp.async.wait_group 1;" ::: "memory")
#define CP_WAIT0()  asm volatile("cp.async.wait_group 0;" ::: "memory")

#define LDSM_X4(r0, r1, r2, r3, addr) \
    asm volatile("ldmatrix.sync.aligned.m8n8.x4.shared.b16 {%0,%1,%2,%3}, [%4];" \
                 : "=r"(r0), "=r"(r1), "=r"(r2), "=r"(r3) : "r"(addr))
#define LDSM_X4T(r0, r1, r2, r3, addr) \
    asm volatile("ldmatrix.sync.aligned.m8n8.x4.trans.shared.b16 {%0,%1,%2,%3}, [%4];" \
                 : "=r"(r0), "=r"(r1), "=r"(r2), "=r"(r3) : "r"(addr))

__device__ __forceinline__ void mma16816(float* c, uint32_t a0, uint32_t a1,
                                         uint32_t a2, uint32_t a3,
                                         uint32_t b0, uint32_t b1) {
    asm volatile(
        "mma.sync.aligned.m16n8k16.row.col.f32.bf16.bf16.f32 "
        "{%0,%1,%2,%3}, {%4,%5,%6,%7}, {%8,%9}, {%0,%1,%2,%3};"
        : "+f"(c[0]), "+f"(c[1]), "+f"(c[2]), "+f"(c[3])
        : "r"(a0), "r"(a1), "r"(a2), "r"(a3), "r"(b0), "r"(b1));
}

__device__ __forceinline__ uint32_t pack_bf2(float lo, float hi) {
    __nv_bfloat162 r = __floats2bfloat162_rn(lo, hi);
    return *(uint32_t*)&r;
}

// ---------------------------------------------------------------------------
// Split fp32 -> (bf16 hi, bf16 lo)
// ---------------------------------------------------------------------------
__global__ __launch_bounds__(256) void split_bf16(
    const float* __restrict__ x, __nv_bfloat16* __restrict__ hi,
    __nv_bfloat16* __restrict__ lo, int n4)
{
    int i = blockIdx.x * 256 + threadIdx.x;
    if (i >= n4) return;
    float4 v = ((const float4*)x)[i];
    float f[4] = {v.x, v.y, v.z, v.w};
    __nv_bfloat16 h[4], l[4];
#pragma unroll
    for (int j = 0; j < 4; j++) {
        h[j] = __float2bfloat16_rn(f[j]);
        l[j] = __float2bfloat16_rn(f[j] - __bfloat162float(h[j]));
    }
    ((__nv_bfloat162*)hi)[2*i]   = __nv_bfloat162(h[0], h[1]);
    ((__nv_bfloat162*)hi)[2*i+1] = __nv_bfloat162(h[2], h[3]);
    ((__nv_bfloat162*)lo)[2*i]   = __nv_bfloat162(l[0], l[1]);
    ((__nv_bfloat162*)lo)[2*i+1] = __nv_bfloat162(l[2], l[3]);
}

// ---------------------------------------------------------------------------
// HMMA bf16-split NT GEMM v2 (R12 config) + split-term reordering:
// Block 256x64, 8 warps (4M x 2N), warp tile 64x32, BK=32, 2-stage cp.async,
// 2 CTAs/SM. Per (kk,mb): 4x hi*hi, then 4x lo*hi, then 4x hi*lo — dependency
// distance 4 MMA issues per accumulator (covers HMMA RAW latency in-warp).
// ---------------------------------------------------------------------------
#define G2_RSTR 80                      /* 32 bf16 + 8 pad = 80 B row */
#define G2_A    (256 * G2_RSTR)         /* 20480 B per A tile */
#define G2_B    (64  * G2_RSTR)         /*  5120 B per B tile */
#define G2_STG  (2 * G2_A + 2 * G2_B)   /* 51200 B per stage */
#define G2_SMEM (2 * G2_STG)            /* 102400 B */

__global__ __launch_bounds__(256, 2)
void gemm2_bf16split(const __nv_bfloat16* __restrict__ Ah,
                     const __nv_bfloat16* __restrict__ Al,
                     const __nv_bfloat16* __restrict__ Bh,
                     const __nv_bfloat16* __restrict__ Bl,
                     float* __restrict__ C, int M, int N, int K)
{
    extern __shared__ char smem[];
    const uint32_t sb = smem_u32(smem);
    const int t   = threadIdx.x;
    const int wid = t >> 5;
    const int l   = t & 31;
    const int m0  = blockIdx.y * 256;
    const int n0  = blockIdx.x * 64;
    const int wm  = (wid & 3) * 64;    // warp M offset (4 warps in M)
    const int wn  = (wid >> 2) * 32;   // warp N offset (2 warps in N)

    // ---- global load mapping (10 x 16B cp.async per thread per stage) ----
    const int grow = t >> 2;           // 0..63
    const int gseg = t & 3;            // 16B segment within 64B k-row
    const uint32_t so = (uint32_t)(grow * G2_RSTR + gseg * 16);
    const __nv_bfloat16* pAh = Ah + (size_t)(m0 + grow) * K + gseg * 8;
    const __nv_bfloat16* pAl = Al + (size_t)(m0 + grow) * K + gseg * 8;
    const __nv_bfloat16* pBh = Bh + (size_t)(n0 + grow) * K + gseg * 8;
    const __nv_bfloat16* pBl = Bl + (size_t)(n0 + grow) * K + gseg * 8;
    const size_t rstep = (size_t)64 * K;

    // ---- ldmatrix relative offsets ----
    const uint32_t aRel = (uint32_t)((wm + (l & 15)) * G2_RSTR + (l >> 4) * 16);
    const uint32_t bRel = (uint32_t)((wn + (l >> 4) * 8 + (l & 7)) * G2_RSTR +
                                     ((l >> 3) & 1) * 16);

    float c[4][4][4];
#pragma unroll
    for (int mb = 0; mb < 4; mb++)
#pragma unroll
        for (int nf = 0; nf < 4; nf++)
#pragma unroll
            for (int e = 0; e < 4; e++) c[mb][nf][e] = 0.f;

    const int nch = K / 32;            // 142

    // issue one chunk's loads into stage s
    auto issue = [&](int ch, int s) {
        const uint32_t base = sb + (uint32_t)s * G2_STG;
        const int ko = ch * 32;
#pragma unroll
        for (int it = 0; it < 4; it++)
            CP_ASYNC16(base + so + it * (64 * G2_RSTR), pAh + ko + it * rstep);
#pragma unroll
        for (int it = 0; it < 4; it++)
            CP_ASYNC16(base + G2_A + so + it * (64 * G2_RSTR), pAl + ko + it * rstep);
        CP_ASYNC16(base + 2*G2_A + so, pBh + ko);
        CP_ASYNC16(base + 2*G2_A + G2_B + so, pBl + ko);
        CP_COMMIT();
    };

    issue(0, 0);

    for (int ch = 0; ch < nch; ++ch) {
        CP_WAIT0();
        __syncthreads();
        if (ch + 1 < nch) issue(ch + 1, (ch + 1) & 1);

        const uint32_t base = sb + (uint32_t)(ch & 1) * G2_STG;
        const uint32_t sAh = base;
        const uint32_t sAl = base + G2_A;
        const uint32_t sBh = base + 2 * G2_A;
        const uint32_t sBl = sBh + G2_B;

#pragma unroll
        for (int kk = 0; kk < 2; kk++) {
            const uint32_t ko = kk * 32;   // 16 elems = 32 B
            uint32_t bh01[4], bh23[4], bl01[4], bl23[4];
            LDSM_X4(bh01[0], bh01[1], bh01[2], bh01[3], sBh + bRel + ko);
            LDSM_X4(bh23[0], bh23[1], bh23[2], bh23[3], sBh + bRel + ko + 16*G2_RSTR);
            LDSM_X4(bl01[0], bl01[1], bl01[2], bl01[3], sBl + bRel + ko);
            LDSM_X4(bl23[0], bl23[1], bl23[2], bl23[3], sBl + bRel + ko + 16*G2_RSTR);

            uint32_t* bh[4] = {&bh01[0], &bh01[2], &bh23[0], &bh23[2]};
            uint32_t* bl[4] = {&bl01[0], &bl01[2], &bl23[0], &bl23[2]};

#pragma unroll
            for (int mb = 0; mb < 4; mb++) {
                uint32_t ah[4], al[4];
                LDSM_X4(ah[0], ah[1], ah[2], ah[3],
                        sAh + aRel + ko + mb * (16 * G2_RSTR));
                LDSM_X4(al[0], al[1], al[2], al[3],
                        sAl + aRel + ko + mb * (16 * G2_RSTR));
                // term 1: hi*hi — 4 independent MMAs
#pragma unroll
                for (int nf = 0; nf < 4; nf++)
                    mma16816(c[mb][nf], ah[0], ah[1], ah[2], ah[3],
                             bh[nf][0], bh[nf][1]);
                // term 2: lo*hi — each accumulator 4 issues after its term 1
#pragma unroll
                for (int nf = 0; nf < 4; nf++)
                    mma16816(c[mb][nf], al[0], al[1], al[2], al[3],
                             bh[nf][0], bh[nf][1]);
                // term 3: hi*lo
#pragma unroll
                for (int nf = 0; nf < 4; nf++)
                    mma16816(c[mb][nf], ah[0], ah[1], ah[2], ah[3],
                             bl[nf][0], bl[nf][1]);
            }
        }
    }

    // ---- epilogue ----
#pragma unroll
    for (int mb = 0; mb < 4; mb++) {
        const int r0 = m0 + wm + mb * 16 + (l >> 2);
#pragma unroll
        for (int nf = 0; nf < 4; nf++) {
            const int col = n0 + wn + nf * 8 + (l & 3) * 2;
            float2 v0 = make_float2(c[mb][nf][0], c[mb][nf][1]);
            float2 v1 = make_float2(c[mb][nf][2], c[mb][nf][3]);
            *(float2*)(C + (size_t)r0 * N + col)       = v0;
            *(float2*)(C + (size_t)(r0 + 8) * N + col) = v1;
        }
    }
}

// ---------------------------------------------------------------------------
// Prep: RoPE (q scaled by 1/8) + bf16 hi/lo split of Q (head-major), K, V
// ---------------------------------------------------------------------------
__global__ __launch_bounds__(256) void prep_qkv()
{
    int idx = blockIdx.x * 256 + threadIdx.x;
    const int total = NB * LQ * 73 * 32;
    if (idx >= total) return;
    int i = idx & 31;
    int rest = idx >> 5;
    int h = rest % 73; rest /= 73;
    int pos = rest % LQ;
    int n = rest / LQ;

    const float* p = g_qkv + (size_t)(n * LQ + pos) * QKVN;

    float y1, y2;
    if (h < 72) {
        float inv = (float)exp(-(double)i * (9.210340371976184 / 32.0));
        float f = (float)pos * inv;
        float c, s;
        sincosf(f, &s, &c);
        float x1 = p[h * 64 + i];
        float x2 = p[h * 64 + i + 32];
        y1 = x1 * c - x2 * s;
        y2 = x2 * c + x1 * s;
        if (h < 71) { y1 *= 0.125f; y2 *= 0.125f; }  // fold attn scale into q
    } else {
        y1 = p[72 * 64 + i];
        y2 = p[72 * 64 + i + 32];
    }

    __nv_bfloat16 h1 = __float2bfloat16_rn(y1);
    __nv_bfloat16 l1 = __float2bfloat16_rn(y1 - __bfloat162float(h1));
    __nv_bfloat16 h2 = __float2bfloat16_rn(y2);
    __nv_bfloat16 l2 = __float2bfloat16_rn(y2 - __bfloat162float(h2));

    if (h < 71) {
        size_t d = ((size_t)(n * HH + h) * LQ + pos) * 64;
        g_q_hi[d + i] = h1;  g_q_hi[d + i + 32] = h2;
        g_q_lo[d + i] = l1;  g_q_lo[d + i + 32] = l2;
    } else if (h == 71) {
        size_t d = ((size_t)n * LQ + pos) * 64;
        g_k_hi[d + i] = h1;  g_k_hi[d + i + 32] = h2;
        g_k_lo[d + i] = l1;  g_k_lo[d + i + 32] = l2;
    } else {
        size_t d = ((size_t)n * LQ + pos) * 64;
        g_v_hi[d + i] = h1;  g_v_hi[d + i + 32] = h2;
        g_v_lo[d + i] = l1;  g_v_lo[d + i + 32] = l2;
    }
}

// ---------------------------------------------------------------------------
// HMMA flash attention (causal, MQA) — unchanged (known good)
// ---------------------------------------------------------------------------
#define FRST   144
#define FTILE  (64 * FRST)
#define FQH    0
#define FQL    FTILE
#define FKV    (2 * FTILE)
#define FBUF   (4 * FTILE)
#define FLASH_SMEM (2 * FTILE + 2 * FBUF)

__global__ __launch_bounds__(128)
void flash_hmma()
{
    const int qt = blockIdx.x;
    const int h  = blockIdx.y;
    const int n  = blockIdx.z;

    extern __shared__ char smem[];
    const uint32_t sb = smem_u32(smem);
    const int t = threadIdx.x, w = t >> 5, l = t & 31;

    {
        const __nv_bfloat16* qh = g_q_hi + ((size_t)(n * HH + h) * LQ + qt * 64) * 64;
        const __nv_bfloat16* ql = g_q_lo + ((size_t)(n * HH + h) * LQ + qt * 64) * 64;
        int r = t >> 1, s0 = (t & 1) * 4;
#pragma unroll
        for (int s = 0; s < 4; s++) {
            CP_ASYNC16(sb + FQH + r * FRST + (s0 + s) * 16, qh + r * 64 + (s0 + s) * 8);
            CP_ASYNC16(sb + FQL + r * FRST + (s0 + s) * 16, ql + r * 64 + (s0 + s) * 8);
        }
        CP_COMMIT();
    }

    const __nv_bfloat16* kvsrc[4] = {
        g_k_hi + (size_t)n * LQ * 64, g_k_lo + (size_t)n * LQ * 64,
        g_v_hi + (size_t)n * LQ * 64, g_v_lo + (size_t)n * LQ * 64 };
    const int kvr = t >> 1, kvs0 = (t & 1) * 4;

    auto load_kv = [&](int kt, int b) {
#pragma unroll
        for (int tile = 0; tile < 4; tile++) {
            const __nv_bfloat16* src = kvsrc[tile] + (size_t)(kt * 64 + kvr) * 64;
            uint32_t dst = sb + FKV + b * FBUF + tile * FTILE + kvr * FRST;
#pragma unroll
            for (int s = 0; s < 4; s++)
                CP_ASYNC16(dst + (kvs0 + s) * 16, src + (kvs0 + s) * 8);
        }
        CP_COMMIT();
    };
    load_kv(0, 0);

    CP_WAIT1();
    __syncthreads();
    uint32_t qhf[4][4], qlf[4][4];
    {
        const uint32_t aRel = (uint32_t)((w * 16 + (l & 15)) * FRST + (l >> 4) * 16);
#pragma unroll
        for (int dc = 0; dc < 4; dc++) {
            LDSM_X4(qhf[dc][0], qhf[dc][1], qhf[dc][2], qhf[dc][3],
                    sb + FQH + aRel + dc * 32);
            LDSM_X4(qlf[dc][0], qlf[dc][1], qlf[dc][2], qlf[dc][3],
                    sb + FQL + aRel + dc * 32);
        }
    }

    float o[8][4];
#pragma unroll
    for (int nf = 0; nf < 8; nf++)
#pragma unroll
        for (int e = 0; e < 4; e++) o[nf][e] = 0.f;
    float mr0 = -3.0e38f, mr1 = -3.0e38f, lr0 = 0.f, lr1 = 0.f;

    const uint32_t bRelK = (uint32_t)(((l >> 4) * 8 + (l & 7)) * FRST + ((l >> 3) & 1) * 16);
    const uint32_t bRelV = (uint32_t)((((l >> 3) & 1) * 8 + (l & 7)) * FRST + (l >> 4) * 16);

    for (int kt = 0; kt <= qt; ++kt) {
        if (kt > 0) __syncthreads();
        if (kt < qt) load_kv(kt + 1, (kt + 1) & 1);
        if (kt < qt) { CP_WAIT1(); } else { CP_WAIT0(); }
        __syncthreads();

        const uint32_t kb = sb + FKV + (kt & 1) * FBUF;
        const uint32_t sKh = kb, sKl = kb + FTILE, sVh = kb + 2*FTILE, sVl = kb + 3*FTILE;

        float s[8][4];
#pragma unroll
        for (int nf = 0; nf < 8; nf++)
#pragma unroll
            for (int e = 0; e < 4; e++) s[nf][e] = 0.f;

#pragma unroll
        for (int dc = 0; dc < 4; dc++) {
            uint32_t kh[4][4], kl[4][4];
#pragma unroll
            for (int np = 0; np < 4; np++) {
                LDSM_X4(kh[np][0], kh[np][1], kh[np][2], kh[np][3],
                        sKh + bRelK + np * 16 * FRST + dc * 32);
                LDSM_X4(kl[np][0], kl[np][1], kl[np][2], kl[np][3],
                        sKl + bRelK + np * 16 * FRST + dc * 32);
            }
#pragma unroll
            for (int np = 0; np < 4; np++) {
                mma16816(s[2*np],   qhf[dc][0], qhf[dc][1], qhf[dc][2], qhf[dc][3], kh[np][0], kh[np][1]);
                mma16816(s[2*np],   qlf[dc][0], qlf[dc][1], qlf[dc][2], qlf[dc][3], kh[np][0], kh[np][1]);
                mma16816(s[2*np],   qhf[dc][0], qhf[dc][1], qhf[dc][2], qhf[dc][3], kl[np][0], kl[np][1]);
                mma16816(s[2*np+1], qhf[dc][0], qhf[dc][1], qhf[dc][2], qhf[dc][3], kh[np][2], kh[np][3]);
                mma16816(s[2*np+1], qlf[dc][0], qlf[dc][1], qlf[dc][2], qlf[dc][3], kh[np][2], kh[np][3]);
                mma16816(s[2*np+1], qhf[dc][0], qhf[dc][1], qhf[dc][2], qhf[dc][3], kl[np][2], kl[np][3]);
            }
        }

        const bool diag = (kt == qt);
        const int rloc0 = w * 16 + (l >> 2);
        const int rloc1 = rloc0 + 8;
        float mx0 = -3.0e38f, mx1 = -3.0e38f;
#pragma unroll
        for (int nf = 0; nf < 8; nf++) {
#pragma unroll
            for (int e = 0; e < 4; e++) {
                if (diag) {
                    int col = nf * 8 + (l & 3) * 2 + (e & 1);
                    int row = (e < 2) ? rloc0 : rloc1;
                    if (col > row) s[nf][e] = -3.0e38f;
                }
                if (e < 2) mx0 = fmaxf(mx0, s[nf][e]);
                else       mx1 = fmaxf(mx1, s[nf][e]);
            }
        }
        mx0 = fmaxf(mx0, __shfl_xor_sync(0xffffffffu, mx0, 1));
        mx0 = fmaxf(mx0, __shfl_xor_sync(0xffffffffu, mx0, 2));
        mx1 = fmaxf(mx1, __shfl_xor_sync(0xffffffffu, mx1, 1));
        mx1 = fmaxf(mx1, __shfl_xor_sync(0xffffffffu, mx1, 2));

        float mn0 = fmaxf(mr0, mx0), mn1 = fmaxf(mr1, mx1);
        float a0 = __expf(mr0 - mn0), a1 = __expf(mr1 - mn1);
        float ls0 = 0.f, ls1 = 0.f;
#pragma unroll
        for (int nf = 0; nf < 8; nf++) {
#pragma unroll
            for (int e = 0; e < 4; e++) {
                float pv = __expf(s[nf][e] - ((e < 2) ? mn0 : mn1));
                s[nf][e] = pv;
                if (e < 2) ls0 += pv; else ls1 += pv;
            }
        }
        ls0 += __shfl_xor_sync(0xffffffffu, ls0, 1);
        ls0 += __shfl_xor_sync(0xffffffffu, ls0, 2);
        ls1 += __shfl_xor_sync(0xffffffffu, ls1, 1);
        ls1 += __shfl_xor_sync(0xffffffffu, ls1, 2);
        lr0 = lr0 * a0 + ls0;  lr1 = lr1 * a1 + ls1;
        mr0 = mn0;             mr1 = mn1;
#pragma unroll
        for (int nf = 0; nf < 8; nf++) {
            o[nf][0] *= a0; o[nf][1] *= a0; o[nf][2] *= a1; o[nf][3] *= a1;
        }

#pragma unroll
        for (int kc = 0; kc < 4; kc++) {
            uint32_t ph[4], pl[4];
#pragma unroll
            for (int half = 0; half < 2; half++) {
                float* sp = s[2*kc + half];
                __nv_bfloat16 h0 = __float2bfloat16_rn(sp[0]);
                __nv_bfloat16 h1 = __float2bfloat16_rn(sp[1]);
                __nv_bfloat16 h2 = __float2bfloat16_rn(sp[2]);
                __nv_bfloat16 h3 = __float2bfloat16_rn(sp[3]);
                ph[2*half]   = pack_bf2(sp[0], sp[1]);
                ph[2*half+1] = pack_bf2(sp[2], sp[3]);
                pl[2*half]   = pack_bf2(sp[0] - __bfloat162float(h0),
                                        sp[1] - __bfloat162float(h1));
                pl[2*half+1] = pack_bf2(sp[2] - __bfloat162float(h2),
                                        sp[3] - __bfloat162float(h3));
            }
            uint32_t pa0 = ph[0], pa1 = ph[1], pa2 = ph[2], pa3 = ph[3];
            uint32_t qa0 = pl[0], qa1 = pl[1], qa2 = pl[2], qa3 = pl[3];

            uint32_t vh[4][4], vl[4][4];
#pragma unroll
            for (int ndp = 0; ndp < 4; ndp++) {
                LDSM_X4T(vh[ndp][0], vh[ndp][1], vh[ndp][2], vh[ndp][3],
                         sVh + bRelV + kc * 16 * FRST + ndp * 32);
                LDSM_X4T(vl[ndp][0], vl[ndp][1], vl[ndp][2], vl[ndp][3],
                         sVl + bRelV + kc * 16 * FRST + ndp * 32);
            }
#pragma unroll
            for (int ndp = 0; ndp < 4; ndp++) {
                mma16816(o[2*ndp],   pa0, pa1, pa2, pa3, vh[ndp][0], vh[ndp][1]);
                mma16816(o[2*ndp],   qa0, qa1, qa2, qa3, vh[ndp][0], vh[ndp][1]);
                mma16816(o[2*ndp],   pa0, pa1, pa2, pa3, vl[ndp][0], vl[ndp][1]);
                mma16816(o[2*ndp+1], pa0, pa1, pa2, pa3, vh[ndp][2], vh[ndp][3]);
                mma16816(o[2*ndp+1], qa0, qa1, qa2, qa3, vh[ndp][2], vh[ndp][3]);
                mma16816(o[2*ndp+1], pa0, pa1, pa2, pa3, vl[ndp][2], vl[ndp][3]);
            }
        }
    }

    float il0 = 1.f / lr0, il1 = 1.f / lr1;
    const int row0 = qt * 64 + w * 16 + (l >> 2);
#pragma unroll
    for (int nf = 0; nf < 8; nf++) {
        const int col = h * 64 + nf * 8 + (l & 3) * 2;
        float v00 = o[nf][0] * il0, v01 = o[nf][1] * il0;
        float v10 = o[nf][2] * il1, v11 = o[nf][3] * il1;
        size_t i0 = (size_t)(n * LQ + row0) * DM + col;
        size_t i1 = (size_t)(n * LQ + row0 + 8) * DM + col;
        __nv_bfloat16 h00 = __float2bfloat16_rn(v00), h01 = __float2bfloat16_rn(v01);
        __nv_bfloat16 h10 = __float2bfloat16_rn(v10), h11 = __float2bfloat16_rn(v11);
        *(__nv_bfloat162*)(g_att_hi + i0) = __nv_bfloat162(h00, h01);
        *(__nv_bfloat162*)(g_att_hi + i1) = __nv_bfloat162(h10, h11);
        *(__nv_bfloat162*)(g_att_lo + i0) =
            __nv_bfloat162(__float2bfloat16_rn(v00 - __bfloat162float(h00)),
                           __float2bfloat16_rn(v01 - __bfloat162float(h01)));
        *(__nv_bfloat162*)(g_att_lo + i1) =
            __nv_bfloat162(__float2bfloat16_rn(v10 - __bfloat162float(h10)),
                           __float2bfloat16_rn(v11 - __bfloat162float(h11)));
    }
}

// ---------------------------------------------------------------------------
extern "C" void kernel_launch(void* const* d_in, const int* in_sizes, int n_in,
                              void* d_out, int out_size)
{
    const float* hidden  = (const float*)d_in[0];
    const float* w_qkv   = (const float*)d_in[1];
    const float* w_dense = (const float*)d_in[2];
    float* out = (float*)d_out;

    float* qkv_ptr;
    cudaGetSymbolAddress((void**)&qkv_ptr, g_qkv);
    __nv_bfloat16 *hid_hi, *hid_lo, *wq_hi, *wq_lo, *wd_hi, *wd_lo, *att_hi, *att_lo;
    cudaGetSymbolAddress((void**)&hid_hi, g_hid_hi);
    cudaGetSymbolAddress((void**)&hid_lo, g_hid_lo);
    cudaGetSymbolAddress((void**)&wq_hi,  g_wq_hi);
    cudaGetSymbolAddress((void**)&wq_lo,  g_wq_lo);
    cudaGetSymbolAddress((void**)&wd_hi,  g_wd_hi);
    cudaGetSymbolAddress((void**)&wd_lo,  g_wd_lo);
    cudaGetSymbolAddress((void**)&att_hi, g_att_hi);
    cudaGetSymbolAddress((void**)&att_lo, g_att_lo);

    cudaFuncSetAttribute(gemm2_bf16split, cudaFuncAttributeMaxDynamicSharedMemorySize,
                         G2_SMEM);
    cudaFuncSetAttribute(flash_hmma, cudaFuncAttributeMaxDynamicSharedMemorySize,
                         FLASH_SMEM);

    // Splits of inputs
    {
        int n4 = MROWS * KDIM / 4;
        split_bf16<<<(n4 + 255) / 256, 256>>>(hidden, hid_hi, hid_lo, n4);
    }
    {
        int n4 = QKVN * KDIM / 4;
        split_bf16<<<(n4 + 255) / 256, 256>>>(w_qkv, wq_hi, wq_lo, n4);
    }
    {
        int n4 = DM * KDIM / 4;
        split_bf16<<<(n4 + 255) / 256, 256>>>(w_dense, wd_hi, wd_lo, n4);
    }

    // 1. QKV projection (HMMA, 256x64 tiles, 2-stage, 2 CTA/SM)
    gemm2_bf16split<<<dim3(QKVN / 64, MROWS / 256), 256, G2_SMEM>>>(
        hid_hi, hid_lo, wq_hi, wq_lo, qkv_ptr, MROWS, QKVN, KDIM);

    // 2. RoPE + hi/lo split of Q (head-major), K, V
    {
        int total = NB * LQ * 73 * 32;
        prep_qkv<<<(total + 255) / 256, 256>>>();
    }

    // 3. HMMA flash attention -> att hi/lo bf16
    flash_hmma<<<dim3(LQ / 64, HH, NB), 128, FLASH_SMEM>>>();

    // 4. Dense projection (HMMA, 256x64 tiles, 2-stage, 2 CTA/SM)
    gemm2_bf16split<<<dim3(DM / 64, MROWS / 256), 256, G2_SMEM>>>(
        att_hi, att_lo, wd_hi, wd_lo, out, MROWS, DM, KDIM);
}

// round 17
// speedup vs baseline: 1.6875x; 1.6875x over previous
#include <cuda_runtime.h>
#include <cuda_bf16.h>
#include <math.h>
#include <stdint.h>

#define NB 2
#define LQ 1024
#define DM 4544
#define HH 71
#define DKVD 64
#define QKVN 4672            /* 73*64 */
#define QKVN_P 4736          /* 37*128 padded */
#define DM_P 4608            /* 36*128 padded */
#define MROWS 2048
#define KDIM 4544            /* 71*64 */

// ---------------------------------------------------------------------------
// Scratch (static device globals — no allocation; zero-initialized)
// ---------------------------------------------------------------------------
__device__ float g_qkv[(size_t)MROWS * QKVN];   // [2048, 4672] fp32 (QKV GEMM out)

__device__ __align__(256) __nv_bfloat16 g_hid_hi[(size_t)MROWS * KDIM];
__device__ __align__(256) __nv_bfloat16 g_hid_lo[(size_t)MROWS * KDIM];
__device__ __align__(256) __nv_bfloat16 g_wq_hi [(size_t)QKVN_P * KDIM];  // padded rows zero
__device__ __align__(256) __nv_bfloat16 g_wq_lo [(size_t)QKVN_P * KDIM];
__device__ __align__(256) __nv_bfloat16 g_wd_hi [(size_t)DM_P   * KDIM];
__device__ __align__(256) __nv_bfloat16 g_wd_lo [(size_t)DM_P   * KDIM];
__device__ __align__(256) __nv_bfloat16 g_att_hi[(size_t)MROWS * DM];
__device__ __align__(256) __nv_bfloat16 g_att_lo[(size_t)MROWS * DM];

// bf16 hi/lo attention operands (written by prep kernel)
__device__ __align__(256) __nv_bfloat16 g_q_hi[(size_t)NB * HH * LQ * DKVD]; // [n][h][pos][64]
__device__ __align__(256) __nv_bfloat16 g_q_lo[(size_t)NB * HH * LQ * DKVD];
__device__ __align__(256) __nv_bfloat16 g_k_hi[(size_t)NB * LQ * DKVD];      // [n][pos][64]
__device__ __align__(256) __nv_bfloat16 g_k_lo[(size_t)NB * LQ * DKVD];
__device__ __align__(256) __nv_bfloat16 g_v_hi[(size_t)NB * LQ * DKVD];
__device__ __align__(256) __nv_bfloat16 g_v_lo[(size_t)NB * LQ * DKVD];

// ---------------------------------------------------------------------------
// Helpers (baseline PTX ISA only — NO tcgen05 / no accel features)
// ---------------------------------------------------------------------------
__device__ __forceinline__ uint32_t smem_u32(const void* p) {
    uint32_t a;
    asm("{ .reg .u64 t; cvta.to.shared.u64 t, %1; cvt.u32.u64 %0, t; }"
        : "=r"(a) : "l"(p));
    return a;
}

#define CP_ASYNC16(smem, gptr) \
    asm volatile("cp.async.cg.shared.global [%0], [%1], 16;" \
                 :: "r"(smem), "l"(gptr) : "memory")
#define CP_COMMIT() asm volatile("cp.async.commit_group;" ::: "memory")
#define CP_WAIT1()  asm volatile("cp.async.wait_group 1;" ::: "memory")
#define CP_WAIT0()  asm volatile("cp.async.wait_group 0;" ::: "memory")

#define LDSM_X4(r0, r1, r2, r3, addr) \
    asm volatile("ldmatrix.sync.aligned.m8n8.x4.shared.b16 {%0,%1,%2,%3}, [%4];" \
                 : "=r"(r0), "=r"(r1), "=r"(r2), "=r"(r3) : "r"(addr))
#define LDSM_X4T(r0, r1, r2, r3, addr) \
    asm volatile("ldmatrix.sync.aligned.m8n8.x4.trans.shared.b16 {%0,%1,%2,%3}, [%4];" \
                 : "=r"(r0), "=r"(r1), "=r"(r2), "=r"(r3) : "r"(addr))

__device__ __forceinline__ void mma16816(float* c, uint32_t a0, uint32_t a1,
                                         uint32_t a2, uint32_t a3,
                                         uint32_t b0, uint32_t b1) {
    asm volatile(
        "mma.sync.aligned.m16n8k16.row.col.f32.bf16.bf16.f32 "
        "{%0,%1,%2,%3}, {%4,%5,%6,%7}, {%8,%9}, {%0,%1,%2,%3};"
        : "+f"(c[0]), "+f"(c[1]), "+f"(c[2]), "+f"(c[3])
        : "r"(a0), "r"(a1), "r"(a2), "r"(a3), "r"(b0), "r"(b1));
}

__device__ __forceinline__ uint32_t pack_bf2(float lo, float hi) {
    __nv_bfloat162 r = __floats2bfloat162_rn(lo, hi);
    return *(uint32_t*)&r;
}

// ---------------------------------------------------------------------------
// Split fp32 -> (bf16 hi, bf16 lo)
// ---------------------------------------------------------------------------
__global__ __launch_bounds__(256) void split_bf16(
    const float* __restrict__ x, __nv_bfloat16* __restrict__ hi,
    __nv_bfloat16* __restrict__ lo, int n4)
{
    int i = blockIdx.x * 256 + threadIdx.x;
    if (i >= n4) return;
    float4 v = ((const float4*)x)[i];
    float f[4] = {v.x, v.y, v.z, v.w};
    __nv_bfloat16 h[4], l[4];
#pragma unroll
    for (int j = 0; j < 4; j++) {
        h[j] = __float2bfloat16_rn(f[j]);
        l[j] = __float2bfloat16_rn(f[j] - __bfloat162float(h[j]));
    }
    ((__nv_bfloat162*)hi)[2*i]   = __nv_bfloat162(h[0], h[1]);
    ((__nv_bfloat162*)hi)[2*i+1] = __nv_bfloat162(h[2], h[3]);
    ((__nv_bfloat162*)lo)[2*i]   = __nv_bfloat162(l[0], l[1]);
    ((__nv_bfloat162*)lo)[2*i+1] = __nv_bfloat162(l[2], l[3]);
}

// ---------------------------------------------------------------------------
// HMMA bf16-split NT GEMM v4: C[M, N_real] = A[M,K] * B[Npad,K]^T
// Block 256x128, 512 threads = 16 warps (4M x 4N), warp tile 64x32, BK=32,
// 2-stage cp.async, 1 CTA/SM (16 warps). smem/MMA ratio improved: smem 1920
// vs tensor 1536 cyc/chunk -> 80% ceiling (vs 67% at Nt=64).
// Epilogue guards col < N_real (B rows padded with zeros to Npad = 128k).
// ---------------------------------------------------------------------------
#define G4_RSTR 80                      /* 32 bf16 + 8 pad = 80 B row */
#define G4_A    (256 * G4_RSTR)         /* 20480 B per A tile */
#define G4_B    (128 * G4_RSTR)         /* 10240 B per B tile */
#define G4_STG  (2 * G4_A + 2 * G4_B)   /* 61440 B per stage */
#define G4_SMEM (2 * G4_STG)            /* 122880 B */

__global__ __launch_bounds__(512, 1)
void gemm4_bf16split(const __nv_bfloat16* __restrict__ Ah,
                     const __nv_bfloat16* __restrict__ Al,
                     const __nv_bfloat16* __restrict__ Bh,
                     const __nv_bfloat16* __restrict__ Bl,
                     float* __restrict__ C, int M, int Nreal, int K)
{
    extern __shared__ char smem[];
    const uint32_t sb = smem_u32(smem);
    const int t   = threadIdx.x;
    const int wid = t >> 5;
    const int l   = t & 31;
    const int m0  = blockIdx.y * 256;
    const int n0  = blockIdx.x * 128;
    const int wm  = (wid & 3) * 64;    // warp M offset (4 warps in M)
    const int wn  = (wid >> 2) * 32;   // warp N offset (4 warps in N)

    // ---- global load mapping: 6 x 16B cp.async per thread per stage ----
    // rows 0..127 via t>>2, 16B seg via t&3; A covers rows r and r+128.
    const int grow = t >> 2;           // 0..127
    const int gseg = t & 3;
    const uint32_t soR  = (uint32_t)(grow * G4_RSTR + gseg * 16);
    const uint32_t soR2 = (uint32_t)((grow + 128) * G4_RSTR + gseg * 16);
    const __nv_bfloat16* pAh = Ah + (size_t)(m0 + grow) * K + gseg * 8;
    const __nv_bfloat16* pAl = Al + (size_t)(m0 + grow) * K + gseg * 8;
    const __nv_bfloat16* pBh = Bh + (size_t)(n0 + grow) * K + gseg * 8;
    const __nv_bfloat16* pBl = Bl + (size_t)(n0 + grow) * K + gseg * 8;
    const size_t rstep = (size_t)128 * K;

    // ---- ldmatrix relative offsets ----
    const uint32_t aRel = (uint32_t)((wm + (l & 15)) * G4_RSTR + (l >> 4) * 16);
    const uint32_t bRel = (uint32_t)((wn + (l >> 4) * 8 + (l & 7)) * G4_RSTR +
                                     ((l >> 3) & 1) * 16);

    float c[4][4][4];
#pragma unroll
    for (int mb = 0; mb < 4; mb++)
#pragma unroll
        for (int nf = 0; nf < 4; nf++)
#pragma unroll
            for (int e = 0; e < 4; e++) c[mb][nf][e] = 0.f;

    const int nch = K / 32;            // 142

    auto issue = [&](int ch, int s) {
        const uint32_t base = sb + (uint32_t)s * G4_STG;
        const int ko = ch * 32;
        CP_ASYNC16(base + soR,          pAh + ko);
        CP_ASYNC16(base + soR2,         pAh + ko + rstep);
        CP_ASYNC16(base + G4_A + soR,   pAl + ko);
        CP_ASYNC16(base + G4_A + soR2,  pAl + ko + rstep);
        CP_ASYNC16(base + 2*G4_A + soR, pBh + ko);
        CP_ASYNC16(base + 2*G4_A + G4_B + soR, pBl + ko);
        CP_COMMIT();
    };

    issue(0, 0);

    for (int ch = 0; ch < nch; ++ch) {
        CP_WAIT0();
        __syncthreads();
        if (ch + 1 < nch) issue(ch + 1, (ch + 1) & 1);

        const uint32_t base = sb + (uint32_t)(ch & 1) * G4_STG;
        const uint32_t sAh = base;
        const uint32_t sAl = base + G4_A;
        const uint32_t sBh = base + 2 * G4_A;
        const uint32_t sBl = sBh + G4_B;

#pragma unroll
        for (int kk = 0; kk < 2; kk++) {
            const uint32_t ko = kk * 32;
            uint32_t bh01[4], bh23[4], bl01[4], bl23[4];
            LDSM_X4(bh01[0], bh01[1], bh01[2], bh01[3], sBh + bRel + ko);
            LDSM_X4(bh23[0], bh23[1], bh23[2], bh23[3], sBh + bRel + ko + 16*G4_RSTR);
            LDSM_X4(bl01[0], bl01[1], bl01[2], bl01[3], sBl + bRel + ko);
            LDSM_X4(bl23[0], bl23[1], bl23[2], bl23[3], sBl + bRel + ko + 16*G4_RSTR);

            uint32_t* bh[4] = {&bh01[0], &bh01[2], &bh23[0], &bh23[2]};
            uint32_t* bl[4] = {&bl01[0], &bl01[2], &bl23[0], &bl23[2]};

#pragma unroll
            for (int mb = 0; mb < 4; mb++) {
                uint32_t ah[4], al[4];
                LDSM_X4(ah[0], ah[1], ah[2], ah[3],
                        sAh + aRel + ko + mb * (16 * G4_RSTR));
                LDSM_X4(al[0], al[1], al[2], al[3],
                        sAl + aRel + ko + mb * (16 * G4_RSTR));
#pragma unroll
                for (int nf = 0; nf < 4; nf++)
                    mma16816(c[mb][nf], ah[0], ah[1], ah[2], ah[3],
                             bh[nf][0], bh[nf][1]);
#pragma unroll
                for (int nf = 0; nf < 4; nf++)
                    mma16816(c[mb][nf], al[0], al[1], al[2], al[3],
                             bh[nf][0], bh[nf][1]);
#pragma unroll
                for (int nf = 0; nf < 4; nf++)
                    mma16816(c[mb][nf], ah[0], ah[1], ah[2], ah[3],
                             bl[nf][0], bl[nf][1]);
            }
        }
    }

    // ---- epilogue (guard padded columns) ----
#pragma unroll
    for (int mb = 0; mb < 4; mb++) {
        const int r0 = m0 + wm + mb * 16 + (l >> 2);
#pragma unroll
        for (int nf = 0; nf < 4; nf++) {
            const int col = n0 + wn + nf * 8 + (l & 3) * 2;
            if (col < Nreal) {
                float2 v0 = make_float2(c[mb][nf][0], c[mb][nf][1]);
                float2 v1 = make_float2(c[mb][nf][2], c[mb][nf][3]);
                *(float2*)(C + (size_t)r0 * Nreal + col)       = v0;
                *(float2*)(C + (size_t)(r0 + 8) * Nreal + col) = v1;
            }
        }
    }
}

// ---------------------------------------------------------------------------
// Prep: RoPE (q scaled by 1/8) + bf16 hi/lo split of Q (head-major), K, V
// ---------------------------------------------------------------------------
__global__ __launch_bounds__(256) void prep_qkv()
{
    int idx = blockIdx.x * 256 + threadIdx.x;
    const int total = NB * LQ * 73 * 32;
    if (idx >= total) return;
    int i = idx & 31;
    int rest = idx >> 5;
    int h = rest % 73; rest /= 73;
    int pos = rest % LQ;
    int n = rest / LQ;

    const float* p = g_qkv + (size_t)(n * LQ + pos) * QKVN;

    float y1, y2;
    if (h < 72) {
        float inv = (float)exp(-(double)i * (9.210340371976184 / 32.0));
        float f = (float)pos * inv;
        float c, s;
        sincosf(f, &s, &c);
        float x1 = p[h * 64 + i];
        float x2 = p[h * 64 + i + 32];
        y1 = x1 * c - x2 * s;
        y2 = x2 * c + x1 * s;
        if (h < 71) { y1 *= 0.125f; y2 *= 0.125f; }
    } else {
        y1 = p[72 * 64 + i];
        y2 = p[72 * 64 + i + 32];
    }

    __nv_bfloat16 h1 = __float2bfloat16_rn(y1);
    __nv_bfloat16 l1 = __float2bfloat16_rn(y1 - __bfloat162float(h1));
    __nv_bfloat16 h2 = __float2bfloat16_rn(y2);
    __nv_bfloat16 l2 = __float2bfloat16_rn(y2 - __bfloat162float(h2));

    if (h < 71) {
        size_t d = ((size_t)(n * HH + h) * LQ + pos) * 64;
        g_q_hi[d + i] = h1;  g_q_hi[d + i + 32] = h2;
        g_q_lo[d + i] = l1;  g_q_lo[d + i + 32] = l2;
    } else if (h == 71) {
        size_t d = ((size_t)n * LQ + pos) * 64;
        g_k_hi[d + i] = h1;  g_k_hi[d + i + 32] = h2;
        g_k_lo[d + i] = l1;  g_k_lo[d + i + 32] = l2;
    } else {
        size_t d = ((size_t)n * LQ + pos) * 64;
        g_v_hi[d + i] = h1;  g_v_hi[d + i + 32] = h2;
        g_v_lo[d + i] = l1;  g_v_lo[d + i + 32] = l2;
    }
}

// ---------------------------------------------------------------------------
// HMMA flash attention (causal, MQA) — unchanged (known good)
// ---------------------------------------------------------------------------
#define FRST   144
#define FTILE  (64 * FRST)
#define FQH    0
#define FQL    FTILE
#define FKV    (2 * FTILE)
#define FBUF   (4 * FTILE)
#define FLASH_SMEM (2 * FTILE + 2 * FBUF)

__global__ __launch_bounds__(128)
void flash_hmma()
{
    const int qt = blockIdx.x;
    const int h  = blockIdx.y;
    const int n  = blockIdx.z;

    extern __shared__ char smem[];
    const uint32_t sb = smem_u32(smem);
    const int t = threadIdx.x, w = t >> 5, l = t & 31;

    {
        const __nv_bfloat16* qh = g_q_hi + ((size_t)(n * HH + h) * LQ + qt * 64) * 64;
        const __nv_bfloat16* ql = g_q_lo + ((size_t)(n * HH + h) * LQ + qt * 64) * 64;
        int r = t >> 1, s0 = (t & 1) * 4;
#pragma unroll
        for (int s = 0; s < 4; s++) {
            CP_ASYNC16(sb + FQH + r * FRST + (s0 + s) * 16, qh + r * 64 + (s0 + s) * 8);
            CP_ASYNC16(sb + FQL + r * FRST + (s0 + s) * 16, ql + r * 64 + (s0 + s) * 8);
        }
        CP_COMMIT();
    }

    const __nv_bfloat16* kvsrc[4] = {
        g_k_hi + (size_t)n * LQ * 64, g_k_lo + (size_t)n * LQ * 64,
        g_v_hi + (size_t)n * LQ * 64, g_v_lo + (size_t)n * LQ * 64 };
    const int kvr = t >> 1, kvs0 = (t & 1) * 4;

    auto load_kv = [&](int kt, int b) {
#pragma unroll
        for (int tile = 0; tile < 4; tile++) {
            const __nv_bfloat16* src = kvsrc[tile] + (size_t)(kt * 64 + kvr) * 64;
            uint32_t dst = sb + FKV + b * FBUF + tile * FTILE + kvr * FRST;
#pragma unroll
            for (int s = 0; s < 4; s++)
                CP_ASYNC16(dst + (kvs0 + s) * 16, src + (kvs0 + s) * 8);
        }
        CP_COMMIT();
    };
    load_kv(0, 0);

    CP_WAIT1();
    __syncthreads();
    uint32_t qhf[4][4], qlf[4][4];
    {
        const uint32_t aRel = (uint32_t)((w * 16 + (l & 15)) * FRST + (l >> 4) * 16);
#pragma unroll
        for (int dc = 0; dc < 4; dc++) {
            LDSM_X4(qhf[dc][0], qhf[dc][1], qhf[dc][2], qhf[dc][3],
                    sb + FQH + aRel + dc * 32);
            LDSM_X4(qlf[dc][0], qlf[dc][1], qlf[dc][2], qlf[dc][3],
                    sb + FQL + aRel + dc * 32);
        }
    }

    float o[8][4];
#pragma unroll
    for (int nf = 0; nf < 8; nf++)
#pragma unroll
        for (int e = 0; e < 4; e++) o[nf][e] = 0.f;
    float mr0 = -3.0e38f, mr1 = -3.0e38f, lr0 = 0.f, lr1 = 0.f;

    const uint32_t bRelK = (uint32_t)(((l >> 4) * 8 + (l & 7)) * FRST + ((l >> 3) & 1) * 16);
    const uint32_t bRelV = (uint32_t)((((l >> 3) & 1) * 8 + (l & 7)) * FRST + (l >> 4) * 16);

    for (int kt = 0; kt <= qt; ++kt) {
        if (kt > 0) __syncthreads();
        if (kt < qt) load_kv(kt + 1, (kt + 1) & 1);
        if (kt < qt) { CP_WAIT1(); } else { CP_WAIT0(); }
        __syncthreads();

        const uint32_t kb = sb + FKV + (kt & 1) * FBUF;
        const uint32_t sKh = kb, sKl = kb + FTILE, sVh = kb + 2*FTILE, sVl = kb + 3*FTILE;

        float s[8][4];
#pragma unroll
        for (int nf = 0; nf < 8; nf++)
#pragma unroll
            for (int e = 0; e < 4; e++) s[nf][e] = 0.f;

#pragma unroll
        for (int dc = 0; dc < 4; dc++) {
            uint32_t kh[4][4], kl[4][4];
#pragma unroll
            for (int np = 0; np < 4; np++) {
                LDSM_X4(kh[np][0], kh[np][1], kh[np][2], kh[np][3],
                        sKh + bRelK + np * 16 * FRST + dc * 32);
                LDSM_X4(kl[np][0], kl[np][1], kl[np][2], kl[np][3],
                        sKl + bRelK + np * 16 * FRST + dc * 32);
            }
#pragma unroll
            for (int np = 0; np < 4; np++) {
                mma16816(s[2*np],   qhf[dc][0], qhf[dc][1], qhf[dc][2], qhf[dc][3], kh[np][0], kh[np][1]);
                mma16816(s[2*np],   qlf[dc][0], qlf[dc][1], qlf[dc][2], qlf[dc][3], kh[np][0], kh[np][1]);
                mma16816(s[2*np],   qhf[dc][0], qhf[dc][1], qhf[dc][2], qhf[dc][3], kl[np][0], kl[np][1]);
                mma16816(s[2*np+1], qhf[dc][0], qhf[dc][1], qhf[dc][2], qhf[dc][3], kh[np][2], kh[np][3]);
                mma16816(s[2*np+1], qlf[dc][0], qlf[dc][1], qlf[dc][2], qlf[dc][3], kh[np][2], kh[np][3]);
                mma16816(s[2*np+1], qhf[dc][0], qhf[dc][1], qhf[dc][2], qhf[dc][3], kl[np][2], kl[np][3]);
            }
        }

        const bool diag = (kt == qt);
        const int rloc0 = w * 16 + (l >> 2);
        const int rloc1 = rloc0 + 8;
        float mx0 = -3.0e38f, mx1 = -3.0e38f;
#pragma unroll
        for (int nf = 0; nf < 8; nf++) {
#pragma unroll
            for (int e = 0; e < 4; e++) {
                if (diag) {
                    int col = nf * 8 + (l & 3) * 2 + (e & 1);
                    int row = (e < 2) ? rloc0 : rloc1;
                    if (col > row) s[nf][e] = -3.0e38f;
                }
                if (e < 2) mx0 = fmaxf(mx0, s[nf][e]);
                else       mx1 = fmaxf(mx1, s[nf][e]);
            }
        }
        mx0 = fmaxf(mx0, __shfl_xor_sync(0xffffffffu, mx0, 1));
        mx0 = fmaxf(mx0, __shfl_xor_sync(0xffffffffu, mx0, 2));
        mx1 = fmaxf(mx1, __shfl_xor_sync(0xffffffffu, mx1, 1));
        mx1 = fmaxf(mx1, __shfl_xor_sync(0xffffffffu, mx1, 2));

        float mn0 = fmaxf(mr0, mx0), mn1 = fmaxf(mr1, mx1);
        float a0 = __expf(mr0 - mn0), a1 = __expf(mr1 - mn1);
        float ls0 = 0.f, ls1 = 0.f;
#pragma unroll
        for (int nf = 0; nf < 8; nf++) {
#pragma unroll
            for (int e = 0; e < 4; e++) {
                float pv = __expf(s[nf][e] - ((e < 2) ? mn0 : mn1));
                s[nf][e] = pv;
                if (e < 2) ls0 += pv; else ls1 += pv;
            }
        }
        ls0 += __shfl_xor_sync(0xffffffffu, ls0, 1);
        ls0 += __shfl_xor_sync(0xffffffffu, ls0, 2);
        ls1 += __shfl_xor_sync(0xffffffffu, ls1, 1);
        ls1 += __shfl_xor_sync(0xffffffffu, ls1, 2);
        lr0 = lr0 * a0 + ls0;  lr1 = lr1 * a1 + ls1;
        mr0 = mn0;             mr1 = mn1;
#pragma unroll
        for (int nf = 0; nf < 8; nf++) {
            o[nf][0] *= a0; o[nf][1] *= a0; o[nf][2] *= a1; o[nf][3] *= a1;
        }

#pragma unroll
        for (int kc = 0; kc < 4; kc++) {
            uint32_t ph[4], pl[4];
#pragma unroll
            for (int half = 0; half < 2; half++) {
                float* sp = s[2*kc + half];
                __nv_bfloat16 h0 = __float2bfloat16_rn(sp[0]);
                __nv_bfloat16 h1 = __float2bfloat16_rn(sp[1]);
                __nv_bfloat16 h2 = __float2bfloat16_rn(sp[2]);
                __nv_bfloat16 h3 = __float2bfloat16_rn(sp[3]);
                ph[2*half]   = pack_bf2(sp[0], sp[1]);
                ph[2*half+1] = pack_bf2(sp[2], sp[3]);
                pl[2*half]   = pack_bf2(sp[0] - __bfloat162float(h0),
                                        sp[1] - __bfloat162float(h1));
                pl[2*half+1] = pack_bf2(sp[2] - __bfloat162float(h2),
                                        sp[3] - __bfloat162float(h3));
            }
            uint32_t pa0 = ph[0], pa1 = ph[1], pa2 = ph[2], pa3 = ph[3];
            uint32_t qa0 = pl[0], qa1 = pl[1], qa2 = pl[2], qa3 = pl[3];

            uint32_t vh[4][4], vl[4][4];
#pragma unroll
            for (int ndp = 0; ndp < 4; ndp++) {
                LDSM_X4T(vh[ndp][0], vh[ndp][1], vh[ndp][2], vh[ndp][3],
                         sVh + bRelV + kc * 16 * FRST + ndp * 32);
                LDSM_X4T(vl[ndp][0], vl[ndp][1], vl[ndp][2], vl[ndp][3],
                         sVl + bRelV + kc * 16 * FRST + ndp * 32);
            }
#pragma unroll
            for (int ndp = 0; ndp < 4; ndp++) {
                mma16816(o[2*ndp],   pa0, pa1, pa2, pa3, vh[ndp][0], vh[ndp][1]);
                mma16816(o[2*ndp],   qa0, qa1, qa2, qa3, vh[ndp][0], vh[ndp][1]);
                mma16816(o[2*ndp],   pa0, pa1, pa2, pa3, vl[ndp][0], vl[ndp][1]);
                mma16816(o[2*ndp+1], pa0, pa1, pa2, pa3, vh[ndp][2], vh[ndp][3]);
                mma16816(o[2*ndp+1], qa0, qa1, qa2, qa3, vh[ndp][2], vh[ndp][3]);
                mma16816(o[2*ndp+1], pa0, pa1, pa2, pa3, vl[ndp][2], vl[ndp][3]);
            }
        }
    }

    float il0 = 1.f / lr0, il1 = 1.f / lr1;
    const int row0 = qt * 64 + w * 16 + (l >> 2);
#pragma unroll
    for (int nf = 0; nf < 8; nf++) {
        const int col = h * 64 + nf * 8 + (l & 3) * 2;
        float v00 = o[nf][0] * il0, v01 = o[nf][1] * il0;
        float v10 = o[nf][2] * il1, v11 = o[nf][3] * il1;
        size_t i0 = (size_t)(n * LQ + row0) * DM + col;
        size_t i1 = (size_t)(n * LQ + row0 + 8) * DM + col;
        __nv_bfloat16 h00 = __float2bfloat16_rn(v00), h01 = __float2bfloat16_rn(v01);
        __nv_bfloat16 h10 = __float2bfloat16_rn(v10), h11 = __float2bfloat16_rn(v11);
        *(__nv_bfloat162*)(g_att_hi + i0) = __nv_bfloat162(h00, h01);
        *(__nv_bfloat162*)(g_att_hi + i1) = __nv_bfloat162(h10, h11);
        *(__nv_bfloat162*)(g_att_lo + i0) =
            __nv_bfloat162(__float2bfloat16_rn(v00 - __bfloat162float(h00)),
                           __float2bfloat16_rn(v01 - __bfloat162float(h01)));
        *(__nv_bfloat162*)(g_att_lo + i1) =
            __nv_bfloat162(__float2bfloat16_rn(v10 - __bfloat162float(h10)),
                           __float2bfloat16_rn(v11 - __bfloat162float(h11)));
    }
}

// ---------------------------------------------------------------------------
extern "C" void kernel_launch(void* const* d_in, const int* in_sizes, int n_in,
                              void* d_out, int out_size)
{
    const float* hidden  = (const float*)d_in[0];
    const float* w_qkv   = (const float*)d_in[1];
    const float* w_dense = (const float*)d_in[2];
    float* out = (float*)d_out;

    float* qkv_ptr;
    cudaGetSymbolAddress((void**)&qkv_ptr, g_qkv);
    __nv_bfloat16 *hid_hi, *hid_lo, *wq_hi, *wq_lo, *wd_hi, *wd_lo, *att_hi, *att_lo;
    cudaGetSymbolAddress((void**)&hid_hi, g_hid_hi);
    cudaGetSymbolAddress((void**)&hid_lo, g_hid_lo);
    cudaGetSymbolAddress((void**)&wq_hi,  g_wq_hi);
    cudaGetSymbolAddress((void**)&wq_lo,  g_wq_lo);
    cudaGetSymbolAddress((void**)&wd_hi,  g_wd_hi);
    cudaGetSymbolAddress((void**)&wd_lo,  g_wd_lo);
    cudaGetSymbolAddress((void**)&att_hi, g_att_hi);
    cudaGetSymbolAddress((void**)&att_lo, g_att_lo);

    cudaFuncSetAttribute(gemm4_bf16split, cudaFuncAttributeMaxDynamicSharedMemorySize,
                         G4_SMEM);
    cudaFuncSetAttribute(flash_hmma, cudaFuncAttributeMaxDynamicSharedMemorySize,
                         FLASH_SMEM);

    // Splits of inputs (weight splits write real rows; padded tails stay zero)
    {
        int n4 = MROWS * KDIM / 4;
        split_bf16<<<(n4 + 255) / 256, 256>>>(hidden, hid_hi, hid_lo, n4);
    }
    {
        int n4 = QKVN * KDIM / 4;
        split_bf16<<<(n4 + 255) / 256, 256>>>(w_qkv, wq_hi, wq_lo, n4);
    }
    {
        int n4 = DM * KDIM / 4;
        split_bf16<<<(n4 + 255) / 256, 256>>>(w_dense, wd_hi, wd_lo, n4);
    }

    // 1. QKV projection (HMMA, 256x128 tiles)  grid 37x8 = 296 CTAs
    gemm4_bf16split<<<dim3(QKVN_P / 128, MROWS / 256), 512, G4_SMEM>>>(
        hid_hi, hid_lo, wq_hi, wq_lo, qkv_ptr, MROWS, QKVN, KDIM);

    // 2. RoPE + hi/lo split of Q (head-major), K, V
    {
        int total = NB * LQ * 73 * 32;
        prep_qkv<<<(total + 255) / 256, 256>>>();
    }

    // 3. HMMA flash attention -> att hi/lo bf16
    flash_hmma<<<dim3(LQ / 64, HH, NB), 128, FLASH_SMEM>>>();

    // 4. Dense projection (HMMA, 256x128 tiles)  grid 36x8 = 288 CTAs
    gemm4_bf16split<<<dim3(DM_P / 128, MROWS / 256), 512, G4_SMEM>>>(
        att_hi, att_lo, wd_hi, wd_lo, out, MROWS, DM, KDIM);
}